// round 10
// baseline (speedup 1.0000x reference)
#include <cuda_runtime.h>

#define KC   100
#define DD   64
#define CAP  224
#define WPB  25
#define TPB  800
#define NBLK 148

// One contiguous zeroed blob: [ g_sum KC*DD | g_sumsq KC | g_cnti KC ]
__device__ float    g_blob[KC * DD + KC + KC];
__device__ unsigned g_done;          // self-resetting ticket (starts 0)

#define G_SUM   (g_blob)
#define G_SUMSQ (g_blob + KC * DD)
#define G_CNTI  ((int*)(g_blob + KC * DD + KC))

// ---------------------------------------------------------------------------
// Per-cluster accumulate: pair-packed LDG.128 gathers, batch-8 MLP.
// lanes 0-15 even list entries, 16-31 odd; each lane one float4 of a row.
// ---------------------------------------------------------------------------
__device__ __forceinline__ void accum_cluster(const float4* __restrict__ d4s,
                                              const unsigned short* __restrict__ lst,
                                              int len, int sub, int half,
                                              float4& A, float& Q) {
    int i = 0;
    for (; i + 16 <= len; i += 16) {
        int e0 = lst[i + 0  + half], e1 = lst[i + 2  + half];
        int e2 = lst[i + 4  + half], e3 = lst[i + 6  + half];
        int e4 = lst[i + 8  + half], e5 = lst[i + 10 + half];
        int e6 = lst[i + 12 + half], e7 = lst[i + 14 + half];
        float4 v0 = __ldcs(d4s + e0 * 16 + sub);
        float4 v1 = __ldcs(d4s + e1 * 16 + sub);
        float4 v2 = __ldcs(d4s + e2 * 16 + sub);
        float4 v3 = __ldcs(d4s + e3 * 16 + sub);
        float4 v4 = __ldcs(d4s + e4 * 16 + sub);
        float4 v5 = __ldcs(d4s + e5 * 16 + sub);
        float4 v6 = __ldcs(d4s + e6 * 16 + sub);
        float4 v7 = __ldcs(d4s + e7 * 16 + sub);
        A.x += v0.x + v1.x + v2.x + v3.x + v4.x + v5.x + v6.x + v7.x;
        A.y += v0.y + v1.y + v2.y + v3.y + v4.y + v5.y + v6.y + v7.y;
        A.z += v0.z + v1.z + v2.z + v3.z + v4.z + v5.z + v6.z + v7.z;
        A.w += v0.w + v1.w + v2.w + v3.w + v4.w + v5.w + v6.w + v7.w;
        Q = fmaf(v0.x, v0.x, Q); Q = fmaf(v0.y, v0.y, Q);
        Q = fmaf(v0.z, v0.z, Q); Q = fmaf(v0.w, v0.w, Q);
        Q = fmaf(v1.x, v1.x, Q); Q = fmaf(v1.y, v1.y, Q);
        Q = fmaf(v1.z, v1.z, Q); Q = fmaf(v1.w, v1.w, Q);
        Q = fmaf(v2.x, v2.x, Q); Q = fmaf(v2.y, v2.y, Q);
        Q = fmaf(v2.z, v2.z, Q); Q = fmaf(v2.w, v2.w, Q);
        Q = fmaf(v3.x, v3.x, Q); Q = fmaf(v3.y, v3.y, Q);
        Q = fmaf(v3.z, v3.z, Q); Q = fmaf(v3.w, v3.w, Q);
        Q = fmaf(v4.x, v4.x, Q); Q = fmaf(v4.y, v4.y, Q);
        Q = fmaf(v4.z, v4.z, Q); Q = fmaf(v4.w, v4.w, Q);
        Q = fmaf(v5.x, v5.x, Q); Q = fmaf(v5.y, v5.y, Q);
        Q = fmaf(v5.z, v5.z, Q); Q = fmaf(v5.w, v5.w, Q);
        Q = fmaf(v6.x, v6.x, Q); Q = fmaf(v6.y, v6.y, Q);
        Q = fmaf(v6.z, v6.z, Q); Q = fmaf(v6.w, v6.w, Q);
        Q = fmaf(v7.x, v7.x, Q); Q = fmaf(v7.y, v7.y, Q);
        Q = fmaf(v7.z, v7.z, Q); Q = fmaf(v7.w, v7.w, Q);
    }
    for (; i + 2 <= len; i += 2) {
        int e = lst[i + half];
        float4 v = __ldcs(d4s + e * 16 + sub);
        A.x += v.x; A.y += v.y; A.z += v.z; A.w += v.w;
        Q = fmaf(v.x, v.x, Q); Q = fmaf(v.y, v.y, Q);
        Q = fmaf(v.z, v.z, Q); Q = fmaf(v.w, v.w, Q);
    }
    if (i < len && half == 0) {
        int e = lst[i];
        float4 v = __ldcs(d4s + e * 16 + sub);
        A.x += v.x; A.y += v.y; A.z += v.z; A.w += v.w;
        Q = fmaf(v.x, v.x, Q); Q = fmaf(v.y, v.y, Q);
        Q = fmaf(v.z, v.z, Q); Q = fmaf(v.w, v.w, Q);
    }
}

// ---------------------------------------------------------------------------
// Single fused kernel: per-block bin -> measured snake assignment ->
// unpredicated register accumulate -> REDG flush -> ticket; the LAST block
// computes the full DBI epilogue (A, Si, row-max, mean) with 25 warps.
// ---------------------------------------------------------------------------
__global__ __launch_bounds__(TPB, 1) void k_accum(const float* __restrict__ data,
                                                  const void* __restrict__ cl,
                                                  int n, float* __restrict__ out) {
    __shared__ unsigned short s_list[KC][CAP];   // 44.8 KB
    __shared__ int s_cnt[KC];
    __shared__ int s_asg[WPB][4];
    __shared__ int s_gc[WPB];
    __shared__ int s_is64;
    __shared__ int s_last;
    // epilogue storage (coexists; ~27 KB more, still < 228 KB/SM)
    __shared__ float s_A[KC * (DD + 1)];
    __shared__ float s_Si[KC];
    __shared__ float s_rcp[KC];
    __shared__ float s_red[WPB];

    const int tid  = threadIdx.x;
    const int lane = tid & 31;
    const int w    = tid >> 5;
    const int sub  = lane & 15;
    const int half = lane >> 4;
    const unsigned FULL = 0xffffffffu;

    const int share = (n + NBLK - 1) / NBLK;
    const long long start = (long long)blockIdx.x * share;
    const int bn = (start < n) ? (int)min((long long)share, (long long)n - start) : 0;

    // ---- label-width detection (front of array; identical in all blocks)
    if (tid == 0) s_is64 = 1;
    for (int c = tid; c < KC; c += TPB) s_cnt[c] = 0;
    if (tid < WPB) s_gc[tid] = 0;
    __syncthreads();
    {
        int lim = min(64, (n - 1) / 2);
        if (tid < lim && ((const int*)cl)[2 * tid + 1] != 0)
            atomicAnd(&s_is64, 0);
    }
    __syncthreads();

    const int is64 = s_is64;
    const long long* cl64 = (const long long*)cl + start;
    const int*       cl32 = (const int*)cl + start;
    const float4*    d4s  = (const float4*)data + start * 16;

    if (bn > 0) {
        // ---- bin (labels read once) --------------------------------------
        for (int i = tid; i < bn; i += TPB) {
            int c = is64 ? (int)__ldg(cl64 + i) : __ldg(cl32 + i);
            int pos = atomicAdd(&s_cnt[c], 1);
            if (pos < CAP) {
                s_list[c][pos] = (unsigned short)i;
            } else {                                   // astronomically rare
                const float4* r = d4s + i * 16;
                float qq = 0.0f;
                for (int u = 0; u < 16; u++) {
                    float4 v = __ldg(r + u);
                    atomicAdd(&G_SUM[c * DD + u * 4 + 0], v.x);
                    atomicAdd(&G_SUM[c * DD + u * 4 + 1], v.y);
                    atomicAdd(&G_SUM[c * DD + u * 4 + 2], v.z);
                    atomicAdd(&G_SUM[c * DD + u * 4 + 3], v.w);
                    qq = fmaf(v.x, v.x, qq); qq = fmaf(v.y, v.y, qq);
                    qq = fmaf(v.z, v.z, qq); qq = fmaf(v.w, v.w, qq);
                }
                atomicAdd(&G_SUMSQ[c], qq);
                atomicAdd(&G_CNTI[c], 1);
            }
        }
        __syncthreads();

        // ---- measured assignment: rank clusters by count, snake-deal -----
        if (tid < KC) {
            int cc = s_cnt[tid];
            int r = 0;
            for (int j = 0; j < KC; j++) {
                int cj = s_cnt[j];
                r += (cj > cc) || (cj == cc && j < tid);
            }
            int q = r / WPB, p = r % WPB;
            int g = (q & 1) ? (WPB - 1 - p) : p;
            int slot = atomicAdd(&s_gc[g], 1);
            s_asg[g][slot] = tid;
            atomicAdd(&G_CNTI[tid], min(cc, CAP));
        }
        __syncthreads();

        // ---- accumulate: warp handles its 4 assigned clusters ------------
        const int c0 = s_asg[w][0], c1 = s_asg[w][1];
        const int c2 = s_asg[w][2], c3 = s_asg[w][3];
        float4 a0 = {0,0,0,0}, a1 = {0,0,0,0}, a2 = {0,0,0,0}, a3 = {0,0,0,0};
        float  q0 = 0, q1 = 0, q2 = 0, q3 = 0;
        accum_cluster(d4s, s_list[c0], min(s_cnt[c0], CAP), sub, half, a0, q0);
        accum_cluster(d4s, s_list[c1], min(s_cnt[c1], CAP), sub, half, a1, q1);
        accum_cluster(d4s, s_list[c2], min(s_cnt[c2], CAP), sub, half, a2, q2);
        accum_cluster(d4s, s_list[c3], min(s_cnt[c3], CAP), sub, half, a3, q3);

        // ---- flush --------------------------------------------------------
#define FLUSH(C, A, Q)                                                       \
        {                                                                    \
            A.x += __shfl_xor_sync(FULL, A.x, 16);                           \
            A.y += __shfl_xor_sync(FULL, A.y, 16);                           \
            A.z += __shfl_xor_sync(FULL, A.z, 16);                           \
            A.w += __shfl_xor_sync(FULL, A.w, 16);                           \
            float qq = Q;                                                    \
            for (int o = 16; o; o >>= 1) qq += __shfl_xor_sync(FULL, qq, o); \
            if (lane < 16) {                                                 \
                float* dst = G_SUM + (C) * DD + sub * 4;                     \
                atomicAdd(dst + 0, A.x);                                     \
                atomicAdd(dst + 1, A.y);                                     \
                atomicAdd(dst + 2, A.z);                                     \
                atomicAdd(dst + 3, A.w);                                     \
            }                                                                \
            if (lane == 0) atomicAdd(&G_SUMSQ[C], qq);                       \
        }
        FLUSH(c0, a0, q0)
        FLUSH(c1, a1, q1)
        FLUSH(c2, a2, q2)
        FLUSH(c3, a3, q3)
#undef FLUSH
    }

    // ---- ticket: last block runs the epilogue ----------------------------
    __threadfence();
    __syncthreads();
    if (tid == 0) {
        unsigned t = atomicAdd(&g_done, 1u);
        s_last = (t == NBLK - 1) ? 1 : 0;
    }
    __syncthreads();
    if (!s_last) return;
    __threadfence();

    // -- A_k and reciprocals
    if (tid < KC) s_rcp[tid] = 1.0f / ((float)__ldg(&G_CNTI[tid]) + 1.0f);
    __syncthreads();
    for (int idx = tid; idx < KC * DD; idx += TPB) {
        int k = idx >> 6, d = idx & 63;
        s_A[k * 65 + d] = (__ldg(&G_SUM[idx]) + 0.001f) * s_rcp[k];
    }
    __syncthreads();

    // -- Si_k = sqrt((0.001 + Q - 2 A.S + n ||A||^2) / (n+1))
    if (tid < KC) {
        int k = tid;
        float nk = (float)__ldg(&G_CNTI[k]), dot = 0.0f, a2 = 0.0f;
#pragma unroll 8
        for (int d = 0; d < DD; d++) {
            float av = s_A[k * 65 + d], sv = __ldg(&G_SUM[k * DD + d]);
            dot = fmaf(av, sv, dot);
            a2  = fmaf(av, av, a2);
        }
        float ss = __ldg(&G_SUMSQ[k]) - 2.0f * dot + nk * a2;
        s_Si[k] = sqrtf((0.001f + ss) * s_rcp[k]);
    }
    __syncthreads();

    // -- row maxes: warp w handles rows w, w+25, w+50, w+75; sum locally
    float rowsum = 0.0f;
    for (int r = w; r < KC; r += WPB) {
        float si = s_Si[r], m = 0.0f;
        for (int j = lane; j < KC; j += 32) {
            if (j == r) continue;
            float d2 = 0.0f;
#pragma unroll 8
            for (int d = 0; d < DD; d++) {
                float df = s_A[r * 65 + d] - s_A[j * 65 + d];
                d2 = fmaf(df, df, d2);
            }
            m = fmaxf(m, (si + s_Si[j]) / sqrtf(d2));
        }
#pragma unroll
        for (int o = 16; o; o >>= 1) m = fmaxf(m, __shfl_xor_sync(FULL, m, o));
        rowsum += m;                       // lane-uniform after reduce
    }
    if (lane == 0) s_red[w] = rowsum;
    __syncthreads();

    if (tid == 0) {
        float tsum = 0.0f;
#pragma unroll
        for (int u = 0; u < WPB; u++) tsum += s_red[u];
        out[0] = tsum / (float)KC;
        g_done = 0;                        // self-reset for next replay
    }
}

// ---------------------------------------------------------------------------
extern "C" void kernel_launch(void* const* d_in, const int* in_sizes, int n_in,
                              void* d_out, int out_size) {
    const float* data;
    const void*  cl;
    int          n;
    if (in_sizes[0] >= in_sizes[1]) {
        data = (const float*)d_in[0]; cl = d_in[1]; n = in_sizes[1];
    } else {
        data = (const float*)d_in[1]; cl = d_in[0]; n = in_sizes[0];
    }

    void* blob = nullptr;
    cudaGetSymbolAddress(&blob, g_blob);
    cudaMemsetAsync(blob, 0, (KC * DD + 2 * KC) * sizeof(float), 0);

    k_accum<<<NBLK, TPB>>>(data, cl, n, (float*)d_out);
}

// round 11
// speedup vs baseline: 1.3104x; 1.3104x over previous
#include <cuda_runtime.h>

#define KC   100
#define DD   64
#define CAP  224
#define WPB  25
#define TPB  800
#define NBLK 148
#define RTPB 512             // k_rows block size (16 warps -> latency hiding)

// One contiguous zeroed blob: [ g_sum KC*DD | g_sumsq KC | g_cnti KC ]
__device__ float    g_blob[KC * DD + KC + KC];
__device__ float    g_rowmax[KC];
__device__ unsigned g_done;          // self-resetting ticket (starts 0)

#define G_SUM   (g_blob)
#define G_SUMSQ (g_blob + KC * DD)
#define G_CNTI  ((int*)(g_blob + KC * DD + KC))

// ---------------------------------------------------------------------------
// Per-cluster accumulate: pair-packed LDG.128 gathers, batch-8 MLP.
// lanes 0-15 even list entries, 16-31 odd; each lane one float4 of a row.
// (UNCHANGED from the 103.2us round-9 version — scheduling is fragile here.)
// ---------------------------------------------------------------------------
__device__ __forceinline__ void accum_cluster(const float4* __restrict__ d4s,
                                              const unsigned short* __restrict__ lst,
                                              int len, int sub, int half,
                                              float4& A, float& Q) {
    int i = 0;
    for (; i + 16 <= len; i += 16) {
        int e0 = lst[i + 0  + half], e1 = lst[i + 2  + half];
        int e2 = lst[i + 4  + half], e3 = lst[i + 6  + half];
        int e4 = lst[i + 8  + half], e5 = lst[i + 10 + half];
        int e6 = lst[i + 12 + half], e7 = lst[i + 14 + half];
        float4 v0 = __ldcs(d4s + e0 * 16 + sub);
        float4 v1 = __ldcs(d4s + e1 * 16 + sub);
        float4 v2 = __ldcs(d4s + e2 * 16 + sub);
        float4 v3 = __ldcs(d4s + e3 * 16 + sub);
        float4 v4 = __ldcs(d4s + e4 * 16 + sub);
        float4 v5 = __ldcs(d4s + e5 * 16 + sub);
        float4 v6 = __ldcs(d4s + e6 * 16 + sub);
        float4 v7 = __ldcs(d4s + e7 * 16 + sub);
        A.x += v0.x + v1.x + v2.x + v3.x + v4.x + v5.x + v6.x + v7.x;
        A.y += v0.y + v1.y + v2.y + v3.y + v4.y + v5.y + v6.y + v7.y;
        A.z += v0.z + v1.z + v2.z + v3.z + v4.z + v5.z + v6.z + v7.z;
        A.w += v0.w + v1.w + v2.w + v3.w + v4.w + v5.w + v6.w + v7.w;
        Q = fmaf(v0.x, v0.x, Q); Q = fmaf(v0.y, v0.y, Q);
        Q = fmaf(v0.z, v0.z, Q); Q = fmaf(v0.w, v0.w, Q);
        Q = fmaf(v1.x, v1.x, Q); Q = fmaf(v1.y, v1.y, Q);
        Q = fmaf(v1.z, v1.z, Q); Q = fmaf(v1.w, v1.w, Q);
        Q = fmaf(v2.x, v2.x, Q); Q = fmaf(v2.y, v2.y, Q);
        Q = fmaf(v2.z, v2.z, Q); Q = fmaf(v2.w, v2.w, Q);
        Q = fmaf(v3.x, v3.x, Q); Q = fmaf(v3.y, v3.y, Q);
        Q = fmaf(v3.z, v3.z, Q); Q = fmaf(v3.w, v3.w, Q);
        Q = fmaf(v4.x, v4.x, Q); Q = fmaf(v4.y, v4.y, Q);
        Q = fmaf(v4.z, v4.z, Q); Q = fmaf(v4.w, v4.w, Q);
        Q = fmaf(v5.x, v5.x, Q); Q = fmaf(v5.y, v5.y, Q);
        Q = fmaf(v5.z, v5.z, Q); Q = fmaf(v5.w, v5.w, Q);
        Q = fmaf(v6.x, v6.x, Q); Q = fmaf(v6.y, v6.y, Q);
        Q = fmaf(v6.z, v6.z, Q); Q = fmaf(v6.w, v6.w, Q);
        Q = fmaf(v7.x, v7.x, Q); Q = fmaf(v7.y, v7.y, Q);
        Q = fmaf(v7.z, v7.z, Q); Q = fmaf(v7.w, v7.w, Q);
    }
    for (; i + 2 <= len; i += 2) {
        int e = lst[i + half];
        float4 v = __ldcs(d4s + e * 16 + sub);
        A.x += v.x; A.y += v.y; A.z += v.z; A.w += v.w;
        Q = fmaf(v.x, v.x, Q); Q = fmaf(v.y, v.y, Q);
        Q = fmaf(v.z, v.z, Q); Q = fmaf(v.w, v.w, Q);
    }
    if (i < len && half == 0) {
        int e = lst[i];
        float4 v = __ldcs(d4s + e * 16 + sub);
        A.x += v.x; A.y += v.y; A.z += v.z; A.w += v.w;
        Q = fmaf(v.x, v.x, Q); Q = fmaf(v.y, v.y, Q);
        Q = fmaf(v.z, v.z, Q); Q = fmaf(v.w, v.w, Q);
    }
}

// ---------------------------------------------------------------------------
// Kernel 1: one contiguous range per block (equal work by construction).
// Bin once -> measured snake assignment -> register accumulate -> REDG flush.
// (UNCHANGED round-9 version.)
// ---------------------------------------------------------------------------
__global__ __launch_bounds__(TPB, 1) void k_accum(const float* __restrict__ data,
                                                  const void* __restrict__ cl,
                                                  int n) {
    __shared__ unsigned short s_list[KC][CAP];   // 44.8 KB
    __shared__ int s_cnt[KC];
    __shared__ int s_asg[WPB][4];
    __shared__ int s_gc[WPB];
    __shared__ int s_is64;

    const int tid  = threadIdx.x;
    const int lane = tid & 31;
    const int w    = tid >> 5;
    const int sub  = lane & 15;
    const int half = lane >> 4;
    const unsigned FULL = 0xffffffffu;

    const int share = (n + NBLK - 1) / NBLK;
    const long long start = (long long)blockIdx.x * share;
    if (start >= n) return;
    const int bn = (int)min((long long)share, (long long)n - start);

    // ---- label-width detection (front of array; identical in all blocks)
    if (tid == 0) s_is64 = 1;
    for (int c = tid; c < KC; c += TPB) s_cnt[c] = 0;
    if (tid < WPB) s_gc[tid] = 0;
    __syncthreads();
    {
        int lim = min(64, (n - 1) / 2);
        if (tid < lim && ((const int*)cl)[2 * tid + 1] != 0)
            atomicAnd(&s_is64, 0);
    }
    __syncthreads();

    const int is64 = s_is64;
    const long long* cl64 = (const long long*)cl + start;
    const int*       cl32 = (const int*)cl + start;
    const float4*    d4s  = (const float4*)data + start * 16;

    // ---- bin (labels read once) ----------------------------------------
    for (int i = tid; i < bn; i += TPB) {
        int c = is64 ? (int)__ldg(cl64 + i) : __ldg(cl32 + i);
        int pos = atomicAdd(&s_cnt[c], 1);
        if (pos < CAP) {
            s_list[c][pos] = (unsigned short)i;
        } else {                                   // astronomically rare
            const float4* r = d4s + i * 16;
            float qq = 0.0f;
            for (int u = 0; u < 16; u++) {
                float4 v = __ldg(r + u);
                atomicAdd(&G_SUM[c * DD + u * 4 + 0], v.x);
                atomicAdd(&G_SUM[c * DD + u * 4 + 1], v.y);
                atomicAdd(&G_SUM[c * DD + u * 4 + 2], v.z);
                atomicAdd(&G_SUM[c * DD + u * 4 + 3], v.w);
                qq = fmaf(v.x, v.x, qq); qq = fmaf(v.y, v.y, qq);
                qq = fmaf(v.z, v.z, qq); qq = fmaf(v.w, v.w, qq);
            }
            atomicAdd(&G_SUMSQ[c], qq);
            atomicAdd(&G_CNTI[c], 1);
        }
    }
    __syncthreads();

    // ---- measured assignment: rank clusters by count, snake-deal to warps
    if (tid < KC) {
        int cc = s_cnt[tid];
        int r = 0;
        for (int j = 0; j < KC; j++) {
            int cj = s_cnt[j];
            r += (cj > cc) || (cj == cc && j < tid);
        }
        int q = r / WPB, p = r % WPB;
        int g = (q & 1) ? (WPB - 1 - p) : p;
        int slot = atomicAdd(&s_gc[g], 1);
        s_asg[g][slot] = tid;
        atomicAdd(&G_CNTI[tid], min(cc, CAP));
    }
    __syncthreads();

    // ---- accumulate: warp handles its 4 assigned clusters ---------------
    const int c0 = s_asg[w][0], c1 = s_asg[w][1];
    const int c2 = s_asg[w][2], c3 = s_asg[w][3];
    float4 a0 = {0,0,0,0}, a1 = {0,0,0,0}, a2 = {0,0,0,0}, a3 = {0,0,0,0};
    float  q0 = 0, q1 = 0, q2 = 0, q3 = 0;
    accum_cluster(d4s, s_list[c0], min(s_cnt[c0], CAP), sub, half, a0, q0);
    accum_cluster(d4s, s_list[c1], min(s_cnt[c1], CAP), sub, half, a1, q1);
    accum_cluster(d4s, s_list[c2], min(s_cnt[c2], CAP), sub, half, a2, q2);
    accum_cluster(d4s, s_list[c3], min(s_cnt[c3], CAP), sub, half, a3, q3);

    // ---- flush ----------------------------------------------------------
#define FLUSH(C, A, Q)                                                       \
    {                                                                        \
        A.x += __shfl_xor_sync(FULL, A.x, 16);                               \
        A.y += __shfl_xor_sync(FULL, A.y, 16);                               \
        A.z += __shfl_xor_sync(FULL, A.z, 16);                               \
        A.w += __shfl_xor_sync(FULL, A.w, 16);                               \
        float qq = Q;                                                        \
        for (int o = 16; o; o >>= 1) qq += __shfl_xor_sync(FULL, qq, o);     \
        if (lane < 16) {                                                     \
            float* dst = G_SUM + (C) * DD + sub * 4;                         \
            atomicAdd(dst + 0, A.x);                                         \
            atomicAdd(dst + 1, A.y);                                         \
            atomicAdd(dst + 2, A.z);                                         \
            atomicAdd(dst + 3, A.w);                                         \
        }                                                                    \
        if (lane == 0) atomicAdd(&G_SUMSQ[C], qq);                           \
    }
    FLUSH(c0, a0, q0)
    FLUSH(c1, a1, q1)
    FLUSH(c2, a2, q2)
    FLUSH(c3, a3, q3)
#undef FLUSH
}

// ---------------------------------------------------------------------------
// Kernel 2: one block per cluster-row, 512 threads. Si derived algebraically
// from the staged A (S = A*(n+1) - 0.001) -> the second 6400-load L2 pass
// is eliminated; only Q is re-read per cluster.
// ---------------------------------------------------------------------------
__global__ __launch_bounds__(RTPB) void k_rows(float* __restrict__ out) {
    __shared__ float s_A[KC * (DD + 1)];   // padded: conflict-free j-reads
    __shared__ float s_Si[KC];
    __shared__ float s_rcp[KC];
    __shared__ float s_red[RTPB / 32];
    __shared__ int   s_last;

    const int tid = threadIdx.x;

    if (tid < KC) s_rcp[tid] = 1.0f / ((float)__ldg(&G_CNTI[tid]) + 1.0f);
    __syncthreads();

    for (int idx = tid; idx < KC * DD; idx += RTPB) {
        int k = idx >> 6, d = idx & 63;
        s_A[k * 65 + d] = (__ldg(&G_SUM[idx]) + 0.001f) * s_rcp[k];
    }
    __syncthreads();

    // Si from A only: dot(A,S) = (n+1)*sum(A^2) - 0.001*sum(A)
    // ss = Q - 2*dot + n*sum(A^2)
    for (int k = tid; k < KC; k += RTPB) {
        float nk = (float)__ldg(&G_CNTI[k]);
        float a2 = 0.0f, sa = 0.0f;
#pragma unroll 8
        for (int d = 0; d < DD; d++) {
            float av = s_A[k * 65 + d];
            a2 = fmaf(av, av, a2);
            sa += av;
        }
        float dot = (nk + 1.0f) * a2 - 0.001f * sa;
        float ss = __ldg(&G_SUMSQ[k]) - 2.0f * dot + nk * a2;
        s_Si[k] = sqrtf((0.001f + ss) * s_rcp[k]);
    }
    __syncthreads();

    const int i = blockIdx.x;
    const float si = s_Si[i];
    float m = 0.0f;
    for (int j = tid; j < KC; j += RTPB) {
        if (j == i) continue;
        float d2 = 0.0f;
#pragma unroll 8
        for (int d = 0; d < DD; d++) {
            float df = s_A[i * 65 + d] - s_A[j * 65 + d];
            d2 = fmaf(df, df, d2);
        }
        m = fmaxf(m, (si + s_Si[j]) / sqrtf(d2));
    }
#pragma unroll
    for (int o = 16; o; o >>= 1) m = fmaxf(m, __shfl_xor_sync(0xffffffffu, m, o));
    if ((tid & 31) == 0) s_red[tid >> 5] = m;
    __syncthreads();

    if (tid == 0) {
        float mm = s_red[0];
#pragma unroll
        for (int u = 1; u < RTPB / 32; u++) mm = fmaxf(mm, s_red[u]);
        g_rowmax[i] = mm;
        __threadfence();
        unsigned t = atomicAdd(&g_done, 1u);
        s_last = (t == KC - 1) ? 1 : 0;
    }
    __syncthreads();

    if (s_last) {                                 // last block: parallel finish
        __threadfence();
        volatile float* rm = g_rowmax;
        float v = (tid < KC) ? rm[tid] : 0.0f;
        if (tid < 128) {
#pragma unroll
            for (int o = 16; o; o >>= 1) v += __shfl_xor_sync(0xffffffffu, v, o);
            if ((tid & 31) == 0) s_red[tid >> 5] = v;
        }
        __syncthreads();
        if (tid == 0) {
            out[0] = (s_red[0] + s_red[1] + s_red[2] + s_red[3]) / (float)KC;
            g_done = 0;                           // self-reset for next replay
        }
    }
}

// ---------------------------------------------------------------------------
extern "C" void kernel_launch(void* const* d_in, const int* in_sizes, int n_in,
                              void* d_out, int out_size) {
    const float* data;
    const void*  cl;
    int          n;
    if (in_sizes[0] >= in_sizes[1]) {
        data = (const float*)d_in[0]; cl = d_in[1]; n = in_sizes[1];
    } else {
        data = (const float*)d_in[1]; cl = d_in[0]; n = in_sizes[0];
    }

    void* blob = nullptr;
    cudaGetSymbolAddress(&blob, g_blob);
    cudaMemsetAsync(blob, 0, (KC * DD + 2 * KC) * sizeof(float), 0);

    k_accum<<<NBLK, TPB>>>(data, cl, n);
    k_rows <<<KC, RTPB>>>((float*)d_out);
}

// round 13
// speedup vs baseline: 1.3316x; 1.0162x over previous
#include <cuda_runtime.h>

#define KC   100
#define DD   64
#define CAP  224
#define WPB  25
#define TPB  800
#define NBLK 148
#define RTPB 512             // k_rows block size (16 warps -> latency hiding)

// One contiguous zeroed blob: [ g_sum KC*DD | g_sumsq KC | g_cnti KC ]
// Zero-initialized at module load; SELF-CLEANED by k_rows' last block so no
// memset node is needed in the graph.
__device__ float    g_blob[KC * DD + KC + KC];
__device__ float    g_rowmax[KC];
__device__ unsigned g_done;          // self-resetting ticket (starts 0)

#define G_SUM   (g_blob)
#define G_SUMSQ (g_blob + KC * DD)
#define G_CNTI  ((int*)(g_blob + KC * DD + KC))

// ---------------------------------------------------------------------------
// Per-cluster accumulate: pair-packed LDG.128 gathers, batch-8 MLP.
// lanes 0-15 even list entries, 16-31 odd; each lane one float4 of a row.
// (FROZEN: the 103.2/100.4us scheduling is fragile — do not touch.)
// ---------------------------------------------------------------------------
__device__ __forceinline__ void accum_cluster(const float4* __restrict__ d4s,
                                              const unsigned short* __restrict__ lst,
                                              int len, int sub, int half,
                                              float4& A, float& Q) {
    int i = 0;
    for (; i + 16 <= len; i += 16) {
        int e0 = lst[i + 0  + half], e1 = lst[i + 2  + half];
        int e2 = lst[i + 4  + half], e3 = lst[i + 6  + half];
        int e4 = lst[i + 8  + half], e5 = lst[i + 10 + half];
        int e6 = lst[i + 12 + half], e7 = lst[i + 14 + half];
        float4 v0 = __ldcs(d4s + e0 * 16 + sub);
        float4 v1 = __ldcs(d4s + e1 * 16 + sub);
        float4 v2 = __ldcs(d4s + e2 * 16 + sub);
        float4 v3 = __ldcs(d4s + e3 * 16 + sub);
        float4 v4 = __ldcs(d4s + e4 * 16 + sub);
        float4 v5 = __ldcs(d4s + e5 * 16 + sub);
        float4 v6 = __ldcs(d4s + e6 * 16 + sub);
        float4 v7 = __ldcs(d4s + e7 * 16 + sub);
        A.x += v0.x + v1.x + v2.x + v3.x + v4.x + v5.x + v6.x + v7.x;
        A.y += v0.y + v1.y + v2.y + v3.y + v4.y + v5.y + v6.y + v7.y;
        A.z += v0.z + v1.z + v2.z + v3.z + v4.z + v5.z + v6.z + v7.z;
        A.w += v0.w + v1.w + v2.w + v3.w + v4.w + v5.w + v6.w + v7.w;
        Q = fmaf(v0.x, v0.x, Q); Q = fmaf(v0.y, v0.y, Q);
        Q = fmaf(v0.z, v0.z, Q); Q = fmaf(v0.w, v0.w, Q);
        Q = fmaf(v1.x, v1.x, Q); Q = fmaf(v1.y, v1.y, Q);
        Q = fmaf(v1.z, v1.z, Q); Q = fmaf(v1.w, v1.w, Q);
        Q = fmaf(v2.x, v2.x, Q); Q = fmaf(v2.y, v2.y, Q);
        Q = fmaf(v2.z, v2.z, Q); Q = fmaf(v2.w, v2.w, Q);
        Q = fmaf(v3.x, v3.x, Q); Q = fmaf(v3.y, v3.y, Q);
        Q = fmaf(v3.z, v3.z, Q); Q = fmaf(v3.w, v3.w, Q);
        Q = fmaf(v4.x, v4.x, Q); Q = fmaf(v4.y, v4.y, Q);
        Q = fmaf(v4.z, v4.z, Q); Q = fmaf(v4.w, v4.w, Q);
        Q = fmaf(v5.x, v5.x, Q); Q = fmaf(v5.y, v5.y, Q);
        Q = fmaf(v5.z, v5.z, Q); Q = fmaf(v5.w, v5.w, Q);
        Q = fmaf(v6.x, v6.x, Q); Q = fmaf(v6.y, v6.y, Q);
        Q = fmaf(v6.z, v6.z, Q); Q = fmaf(v6.w, v6.w, Q);
        Q = fmaf(v7.x, v7.x, Q); Q = fmaf(v7.y, v7.y, Q);
        Q = fmaf(v7.z, v7.z, Q); Q = fmaf(v7.w, v7.w, Q);
    }
    for (; i + 2 <= len; i += 2) {
        int e = lst[i + half];
        float4 v = __ldcs(d4s + e * 16 + sub);
        A.x += v.x; A.y += v.y; A.z += v.z; A.w += v.w;
        Q = fmaf(v.x, v.x, Q); Q = fmaf(v.y, v.y, Q);
        Q = fmaf(v.z, v.z, Q); Q = fmaf(v.w, v.w, Q);
    }
    if (i < len && half == 0) {
        int e = lst[i];
        float4 v = __ldcs(d4s + e * 16 + sub);
        A.x += v.x; A.y += v.y; A.z += v.z; A.w += v.w;
        Q = fmaf(v.x, v.x, Q); Q = fmaf(v.y, v.y, Q);
        Q = fmaf(v.z, v.z, Q); Q = fmaf(v.w, v.w, Q);
    }
}

// ---------------------------------------------------------------------------
// Kernel 1: one contiguous range per block (equal work by construction).
// Bin once -> measured snake assignment -> register accumulate -> REDG flush.
// (FROZEN round-9/11 version.)
// ---------------------------------------------------------------------------
__global__ __launch_bounds__(TPB, 1) void k_accum(const float* __restrict__ data,
                                                  const void* __restrict__ cl,
                                                  int n) {
    __shared__ unsigned short s_list[KC][CAP];   // 44.8 KB
    __shared__ int s_cnt[KC];
    __shared__ int s_asg[WPB][4];
    __shared__ int s_gc[WPB];
    __shared__ int s_is64;

    const int tid  = threadIdx.x;
    const int lane = tid & 31;
    const int w    = tid >> 5;
    const int sub  = lane & 15;
    const int half = lane >> 4;
    const unsigned FULL = 0xffffffffu;

    const int share = (n + NBLK - 1) / NBLK;
    const long long start = (long long)blockIdx.x * share;
    if (start >= n) return;
    const int bn = (int)min((long long)share, (long long)n - start);

    // ---- label-width detection (front of array; identical in all blocks)
    if (tid == 0) s_is64 = 1;
    for (int c = tid; c < KC; c += TPB) s_cnt[c] = 0;
    if (tid < WPB) s_gc[tid] = 0;
    __syncthreads();
    {
        int lim = min(64, (n - 1) / 2);
        if (tid < lim && ((const int*)cl)[2 * tid + 1] != 0)
            atomicAnd(&s_is64, 0);
    }
    __syncthreads();

    const int is64 = s_is64;
    const long long* cl64 = (const long long*)cl + start;
    const int*       cl32 = (const int*)cl + start;
    const float4*    d4s  = (const float4*)data + start * 16;

    // ---- bin (labels read once) ----------------------------------------
    for (int i = tid; i < bn; i += TPB) {
        int c = is64 ? (int)__ldg(cl64 + i) : __ldg(cl32 + i);
        int pos = atomicAdd(&s_cnt[c], 1);
        if (pos < CAP) {
            s_list[c][pos] = (unsigned short)i;
        } else {                                   // astronomically rare
            const float4* r = d4s + i * 16;
            float qq = 0.0f;
            for (int u = 0; u < 16; u++) {
                float4 v = __ldg(r + u);
                atomicAdd(&G_SUM[c * DD + u * 4 + 0], v.x);
                atomicAdd(&G_SUM[c * DD + u * 4 + 1], v.y);
                atomicAdd(&G_SUM[c * DD + u * 4 + 2], v.z);
                atomicAdd(&G_SUM[c * DD + u * 4 + 3], v.w);
                qq = fmaf(v.x, v.x, qq); qq = fmaf(v.y, v.y, qq);
                qq = fmaf(v.z, v.z, qq); qq = fmaf(v.w, v.w, qq);
            }
            atomicAdd(&G_SUMSQ[c], qq);
            atomicAdd(&G_CNTI[c], 1);
        }
    }
    __syncthreads();

    // ---- measured assignment: rank clusters by count, snake-deal to warps
    if (tid < KC) {
        int cc = s_cnt[tid];
        int r = 0;
        for (int j = 0; j < KC; j++) {
            int cj = s_cnt[j];
            r += (cj > cc) || (cj == cc && j < tid);
        }
        int q = r / WPB, p = r % WPB;
        int g = (q & 1) ? (WPB - 1 - p) : p;
        int slot = atomicAdd(&s_gc[g], 1);
        s_asg[g][slot] = tid;
        atomicAdd(&G_CNTI[tid], min(cc, CAP));
    }
    __syncthreads();

    // ---- accumulate: warp handles its 4 assigned clusters ---------------
    const int c0 = s_asg[w][0], c1 = s_asg[w][1];
    const int c2 = s_asg[w][2], c3 = s_asg[w][3];
    float4 a0 = {0,0,0,0}, a1 = {0,0,0,0}, a2 = {0,0,0,0}, a3 = {0,0,0,0};
    float  q0 = 0, q1 = 0, q2 = 0, q3 = 0;
    accum_cluster(d4s, s_list[c0], min(s_cnt[c0], CAP), sub, half, a0, q0);
    accum_cluster(d4s, s_list[c1], min(s_cnt[c1], CAP), sub, half, a1, q1);
    accum_cluster(d4s, s_list[c2], min(s_cnt[c2], CAP), sub, half, a2, q2);
    accum_cluster(d4s, s_list[c3], min(s_cnt[c3], CAP), sub, half, a3, q3);

    // ---- flush ----------------------------------------------------------
#define FLUSH(C, A, Q)                                                       \
    {                                                                        \
        A.x += __shfl_xor_sync(FULL, A.x, 16);                               \
        A.y += __shfl_xor_sync(FULL, A.y, 16);                               \
        A.z += __shfl_xor_sync(FULL, A.z, 16);                               \
        A.w += __shfl_xor_sync(FULL, A.w, 16);                               \
        float qq = Q;                                                        \
        for (int o = 16; o; o >>= 1) qq += __shfl_xor_sync(FULL, qq, o);     \
        if (lane < 16) {                                                     \
            float* dst = G_SUM + (C) * DD + sub * 4;                         \
            atomicAdd(dst + 0, A.x);                                         \
            atomicAdd(dst + 1, A.y);                                         \
            atomicAdd(dst + 2, A.z);                                         \
            atomicAdd(dst + 3, A.w);                                         \
        }                                                                    \
        if (lane == 0) atomicAdd(&G_SUMSQ[C], qq);                           \
    }
    FLUSH(c0, a0, q0)
    FLUSH(c1, a1, q1)
    FLUSH(c2, a2, q2)
    FLUSH(c3, a3, q3)
#undef FLUSH
}

// ---------------------------------------------------------------------------
// Kernel 2: one block per cluster-row, 512 threads. Si derived algebraically
// from the staged A. The LAST ticketed block finishes the scalar AND re-zeros
// g_blob for the next replay (replaces the memset graph node).
// ---------------------------------------------------------------------------
__global__ __launch_bounds__(RTPB) void k_rows(float* __restrict__ out) {
    __shared__ float s_A[KC * (DD + 1)];   // padded: conflict-free j-reads
    __shared__ float s_Si[KC];
    __shared__ float s_rcp[KC];
    __shared__ float s_red[RTPB / 32];
    __shared__ int   s_last;

    const int tid = threadIdx.x;

    if (tid < KC) s_rcp[tid] = 1.0f / ((float)__ldg(&G_CNTI[tid]) + 1.0f);
    __syncthreads();

    for (int idx = tid; idx < KC * DD; idx += RTPB) {
        int k = idx >> 6, d = idx & 63;
        s_A[k * 65 + d] = (__ldg(&G_SUM[idx]) + 0.001f) * s_rcp[k];
    }
    __syncthreads();

    // Si from A only: dot(A,S) = (n+1)*sum(A^2) - 0.001*sum(A)
    // ss = Q - 2*dot + n*sum(A^2)
    for (int k = tid; k < KC; k += RTPB) {
        float nk = (float)__ldg(&G_CNTI[k]);
        float a2 = 0.0f, sa = 0.0f;
#pragma unroll 8
        for (int d = 0; d < DD; d++) {
            float av = s_A[k * 65 + d];
            a2 = fmaf(av, av, a2);
            sa += av;
        }
        float dot = (nk + 1.0f) * a2 - 0.001f * sa;
        float ss = __ldg(&G_SUMSQ[k]) - 2.0f * dot + nk * a2;
        s_Si[k] = sqrtf((0.001f + ss) * s_rcp[k]);
    }
    __syncthreads();

    const int i = blockIdx.x;
    const float si = s_Si[i];
    float m = 0.0f;
    for (int j = tid; j < KC; j += RTPB) {
        if (j == i) continue;
        float d2 = 0.0f;
#pragma unroll 8
        for (int d = 0; d < DD; d++) {
            float df = s_A[i * 65 + d] - s_A[j * 65 + d];
            d2 = fmaf(df, df, d2);
        }
        m = fmaxf(m, (si + s_Si[j]) / sqrtf(d2));
    }
#pragma unroll
    for (int o = 16; o; o >>= 1) m = fmaxf(m, __shfl_xor_sync(0xffffffffu, m, o));
    if ((tid & 31) == 0) s_red[tid >> 5] = m;
    __syncthreads();

    if (tid == 0) {
        float mm = s_red[0];
#pragma unroll
        for (int u = 1; u < RTPB / 32; u++) mm = fmaxf(mm, s_red[u]);
        g_rowmax[i] = mm;
        __threadfence();
        unsigned t = atomicAdd(&g_done, 1u);
        s_last = (t == KC - 1) ? 1 : 0;
    }
    __syncthreads();

    if (s_last) {                                 // last block: finish + clean
        __threadfence();
        volatile float* rm = g_rowmax;
        float v = (tid < KC) ? rm[tid] : 0.0f;
        if (tid < 128) {
#pragma unroll
            for (int o = 16; o; o >>= 1) v += __shfl_xor_sync(0xffffffffu, v, o);
            if ((tid & 31) == 0) s_red[tid >> 5] = v;
        }
        __syncthreads();
        // self-clean the blob for the next replay (all blocks are done:
        // they incremented the ticket only after their last G_SUM read)
        for (int idx = tid; idx < KC * DD + 2 * KC; idx += RTPB)
            g_blob[idx] = 0.0f;
        if (tid == 0) {
            out[0] = (s_red[0] + s_red[1] + s_red[2] + s_red[3]) / (float)KC;
            g_done = 0;                           // self-reset for next replay
        }
    }
}

// ---------------------------------------------------------------------------
extern "C" void kernel_launch(void* const* d_in, const int* in_sizes, int n_in,
                              void* d_out, int out_size) {
    const float* data;
    const void*  cl;
    int          n;
    if (in_sizes[0] >= in_sizes[1]) {
        data = (const float*)d_in[0]; cl = d_in[1]; n = in_sizes[1];
    } else {
        data = (const float*)d_in[1]; cl = d_in[0]; n = in_sizes[0];
    }

    // g_blob is zeroed at module load and self-cleaned by k_rows each run:
    // no memset node needed.
    k_accum<<<NBLK, TPB>>>(data, cl, n);
    k_rows <<<KC, RTPB>>>((float*)d_out);
}

// round 14
// speedup vs baseline: 1.3553x; 1.0178x over previous
#include <cuda_runtime.h>

#define KC   100
#define DD   64
#define CAP  224
#define WPB  25
#define TPB  800
#define NBLK 148
#define RTPB 512             // k_rows block size (16 warps -> latency hiding)

// One contiguous zeroed blob: [ g_sum KC*DD | g_sumsq KC | g_cnti KC ]
// Zero-initialized at module load; SELF-CLEANED by k_rows' last block so no
// memset node is needed in the graph.
__device__ float    g_blob[KC * DD + KC + KC];
__device__ float    g_rowmax[KC];
__device__ unsigned g_done;          // self-resetting ticket (starts 0)

#define G_SUM   (g_blob)
#define G_SUMSQ (g_blob + KC * DD)
#define G_CNTI  ((int*)(g_blob + KC * DD + KC))

// ---------------------------------------------------------------------------
// Per-cluster accumulate: pair-packed LDG.128 gathers, batch-8 MLP.
// lanes 0-15 even list entries, 16-31 odd; each lane one float4 of a row.
// (FROZEN: the 103.2/100.4us scheduling is fragile — do not touch.)
// ---------------------------------------------------------------------------
__device__ __forceinline__ void accum_cluster(const float4* __restrict__ d4s,
                                              const unsigned short* __restrict__ lst,
                                              int len, int sub, int half,
                                              float4& A, float& Q) {
    int i = 0;
    for (; i + 16 <= len; i += 16) {
        int e0 = lst[i + 0  + half], e1 = lst[i + 2  + half];
        int e2 = lst[i + 4  + half], e3 = lst[i + 6  + half];
        int e4 = lst[i + 8  + half], e5 = lst[i + 10 + half];
        int e6 = lst[i + 12 + half], e7 = lst[i + 14 + half];
        float4 v0 = __ldcs(d4s + e0 * 16 + sub);
        float4 v1 = __ldcs(d4s + e1 * 16 + sub);
        float4 v2 = __ldcs(d4s + e2 * 16 + sub);
        float4 v3 = __ldcs(d4s + e3 * 16 + sub);
        float4 v4 = __ldcs(d4s + e4 * 16 + sub);
        float4 v5 = __ldcs(d4s + e5 * 16 + sub);
        float4 v6 = __ldcs(d4s + e6 * 16 + sub);
        float4 v7 = __ldcs(d4s + e7 * 16 + sub);
        A.x += v0.x + v1.x + v2.x + v3.x + v4.x + v5.x + v6.x + v7.x;
        A.y += v0.y + v1.y + v2.y + v3.y + v4.y + v5.y + v6.y + v7.y;
        A.z += v0.z + v1.z + v2.z + v3.z + v4.z + v5.z + v6.z + v7.z;
        A.w += v0.w + v1.w + v2.w + v3.w + v4.w + v5.w + v6.w + v7.w;
        Q = fmaf(v0.x, v0.x, Q); Q = fmaf(v0.y, v0.y, Q);
        Q = fmaf(v0.z, v0.z, Q); Q = fmaf(v0.w, v0.w, Q);
        Q = fmaf(v1.x, v1.x, Q); Q = fmaf(v1.y, v1.y, Q);
        Q = fmaf(v1.z, v1.z, Q); Q = fmaf(v1.w, v1.w, Q);
        Q = fmaf(v2.x, v2.x, Q); Q = fmaf(v2.y, v2.y, Q);
        Q = fmaf(v2.z, v2.z, Q); Q = fmaf(v2.w, v2.w, Q);
        Q = fmaf(v3.x, v3.x, Q); Q = fmaf(v3.y, v3.y, Q);
        Q = fmaf(v3.z, v3.z, Q); Q = fmaf(v3.w, v3.w, Q);
        Q = fmaf(v4.x, v4.x, Q); Q = fmaf(v4.y, v4.y, Q);
        Q = fmaf(v4.z, v4.z, Q); Q = fmaf(v4.w, v4.w, Q);
        Q = fmaf(v5.x, v5.x, Q); Q = fmaf(v5.y, v5.y, Q);
        Q = fmaf(v5.z, v5.z, Q); Q = fmaf(v5.w, v5.w, Q);
        Q = fmaf(v6.x, v6.x, Q); Q = fmaf(v6.y, v6.y, Q);
        Q = fmaf(v6.z, v6.z, Q); Q = fmaf(v6.w, v6.w, Q);
        Q = fmaf(v7.x, v7.x, Q); Q = fmaf(v7.y, v7.y, Q);
        Q = fmaf(v7.z, v7.z, Q); Q = fmaf(v7.w, v7.w, Q);
    }
    for (; i + 2 <= len; i += 2) {
        int e = lst[i + half];
        float4 v = __ldcs(d4s + e * 16 + sub);
        A.x += v.x; A.y += v.y; A.z += v.z; A.w += v.w;
        Q = fmaf(v.x, v.x, Q); Q = fmaf(v.y, v.y, Q);
        Q = fmaf(v.z, v.z, Q); Q = fmaf(v.w, v.w, Q);
    }
    if (i < len && half == 0) {
        int e = lst[i];
        float4 v = __ldcs(d4s + e * 16 + sub);
        A.x += v.x; A.y += v.y; A.z += v.z; A.w += v.w;
        Q = fmaf(v.x, v.x, Q); Q = fmaf(v.y, v.y, Q);
        Q = fmaf(v.z, v.z, Q); Q = fmaf(v.w, v.w, Q);
    }
}

// ---------------------------------------------------------------------------
// Kernel 1: one contiguous range per block (equal work by construction).
// Bin once -> measured snake assignment -> register accumulate -> REDG flush.
// (FROZEN round-9/11 version.)
// ---------------------------------------------------------------------------
__global__ __launch_bounds__(TPB, 1) void k_accum(const float* __restrict__ data,
                                                  const void* __restrict__ cl,
                                                  int n) {
    __shared__ unsigned short s_list[KC][CAP];   // 44.8 KB
    __shared__ int s_cnt[KC];
    __shared__ int s_asg[WPB][4];
    __shared__ int s_gc[WPB];
    __shared__ int s_is64;

    const int tid  = threadIdx.x;
    const int lane = tid & 31;
    const int w    = tid >> 5;
    const int sub  = lane & 15;
    const int half = lane >> 4;
    const unsigned FULL = 0xffffffffu;

    const int share = (n + NBLK - 1) / NBLK;
    const long long start = (long long)blockIdx.x * share;
    if (start >= n) return;
    const int bn = (int)min((long long)share, (long long)n - start);

    // ---- label-width detection (front of array; identical in all blocks)
    if (tid == 0) s_is64 = 1;
    for (int c = tid; c < KC; c += TPB) s_cnt[c] = 0;
    if (tid < WPB) s_gc[tid] = 0;
    __syncthreads();
    {
        int lim = min(64, (n - 1) / 2);
        if (tid < lim && ((const int*)cl)[2 * tid + 1] != 0)
            atomicAnd(&s_is64, 0);
    }
    __syncthreads();

    const int is64 = s_is64;
    const long long* cl64 = (const long long*)cl + start;
    const int*       cl32 = (const int*)cl + start;
    const float4*    d4s  = (const float4*)data + start * 16;

    // ---- bin (labels read once) ----------------------------------------
    for (int i = tid; i < bn; i += TPB) {
        int c = is64 ? (int)__ldg(cl64 + i) : __ldg(cl32 + i);
        int pos = atomicAdd(&s_cnt[c], 1);
        if (pos < CAP) {
            s_list[c][pos] = (unsigned short)i;
        } else {                                   // astronomically rare
            const float4* r = d4s + i * 16;
            float qq = 0.0f;
            for (int u = 0; u < 16; u++) {
                float4 v = __ldg(r + u);
                atomicAdd(&G_SUM[c * DD + u * 4 + 0], v.x);
                atomicAdd(&G_SUM[c * DD + u * 4 + 1], v.y);
                atomicAdd(&G_SUM[c * DD + u * 4 + 2], v.z);
                atomicAdd(&G_SUM[c * DD + u * 4 + 3], v.w);
                qq = fmaf(v.x, v.x, qq); qq = fmaf(v.y, v.y, qq);
                qq = fmaf(v.z, v.z, qq); qq = fmaf(v.w, v.w, qq);
            }
            atomicAdd(&G_SUMSQ[c], qq);
            atomicAdd(&G_CNTI[c], 1);
        }
    }
    __syncthreads();

    // ---- measured assignment: rank clusters by count, snake-deal to warps
    if (tid < KC) {
        int cc = s_cnt[tid];
        int r = 0;
        for (int j = 0; j < KC; j++) {
            int cj = s_cnt[j];
            r += (cj > cc) || (cj == cc && j < tid);
        }
        int q = r / WPB, p = r % WPB;
        int g = (q & 1) ? (WPB - 1 - p) : p;
        int slot = atomicAdd(&s_gc[g], 1);
        s_asg[g][slot] = tid;
        atomicAdd(&G_CNTI[tid], min(cc, CAP));
    }
    __syncthreads();

    // ---- accumulate: warp handles its 4 assigned clusters ---------------
    const int c0 = s_asg[w][0], c1 = s_asg[w][1];
    const int c2 = s_asg[w][2], c3 = s_asg[w][3];
    float4 a0 = {0,0,0,0}, a1 = {0,0,0,0}, a2 = {0,0,0,0}, a3 = {0,0,0,0};
    float  q0 = 0, q1 = 0, q2 = 0, q3 = 0;
    accum_cluster(d4s, s_list[c0], min(s_cnt[c0], CAP), sub, half, a0, q0);
    accum_cluster(d4s, s_list[c1], min(s_cnt[c1], CAP), sub, half, a1, q1);
    accum_cluster(d4s, s_list[c2], min(s_cnt[c2], CAP), sub, half, a2, q2);
    accum_cluster(d4s, s_list[c3], min(s_cnt[c3], CAP), sub, half, a3, q3);

    // ---- flush ----------------------------------------------------------
#define FLUSH(C, A, Q)                                                       \
    {                                                                        \
        A.x += __shfl_xor_sync(FULL, A.x, 16);                               \
        A.y += __shfl_xor_sync(FULL, A.y, 16);                               \
        A.z += __shfl_xor_sync(FULL, A.z, 16);                               \
        A.w += __shfl_xor_sync(FULL, A.w, 16);                               \
        float qq = Q;                                                        \
        for (int o = 16; o; o >>= 1) qq += __shfl_xor_sync(FULL, qq, o);     \
        if (lane < 16) {                                                     \
            float* dst = G_SUM + (C) * DD + sub * 4;                         \
            atomicAdd(dst + 0, A.x);                                         \
            atomicAdd(dst + 1, A.y);                                         \
            atomicAdd(dst + 2, A.z);                                         \
            atomicAdd(dst + 3, A.w);                                         \
        }                                                                    \
        if (lane == 0) atomicAdd(&G_SUMSQ[C], qq);                           \
    }
    FLUSH(c0, a0, q0)
    FLUSH(c1, a1, q1)
    FLUSH(c2, a2, q2)
    FLUSH(c3, a3, q3)
#undef FLUSH
}

// ---------------------------------------------------------------------------
// Kernel 2: one block per cluster-row, 512 threads. Si derived algebraically
// from the staged A. The LAST ticketed block finishes the scalar AND re-zeros
// g_blob for the next replay (replaces the memset graph node).
// ---------------------------------------------------------------------------
__global__ __launch_bounds__(RTPB) void k_rows(float* __restrict__ out) {
    __shared__ float s_A[KC * (DD + 1)];   // padded: conflict-free j-reads
    __shared__ float s_Si[KC];
    __shared__ float s_rcp[KC];
    __shared__ float s_red[RTPB / 32];
    __shared__ int   s_last;

    const int tid = threadIdx.x;

    if (tid < KC) s_rcp[tid] = 1.0f / ((float)__ldg(&G_CNTI[tid]) + 1.0f);
    __syncthreads();

    for (int idx = tid; idx < KC * DD; idx += RTPB) {
        int k = idx >> 6, d = idx & 63;
        s_A[k * 65 + d] = (__ldg(&G_SUM[idx]) + 0.001f) * s_rcp[k];
    }
    __syncthreads();

    // Si from A only: dot(A,S) = (n+1)*sum(A^2) - 0.001*sum(A)
    // ss = Q - 2*dot + n*sum(A^2)
    for (int k = tid; k < KC; k += RTPB) {
        float nk = (float)__ldg(&G_CNTI[k]);
        float a2 = 0.0f, sa = 0.0f;
#pragma unroll 8
        for (int d = 0; d < DD; d++) {
            float av = s_A[k * 65 + d];
            a2 = fmaf(av, av, a2);
            sa += av;
        }
        float dot = (nk + 1.0f) * a2 - 0.001f * sa;
        float ss = __ldg(&G_SUMSQ[k]) - 2.0f * dot + nk * a2;
        s_Si[k] = sqrtf((0.001f + ss) * s_rcp[k]);
    }
    __syncthreads();

    const int i = blockIdx.x;
    const float si = s_Si[i];
    float m = 0.0f;
    for (int j = tid; j < KC; j += RTPB) {
        if (j == i) continue;
        float d2 = 0.0f;
#pragma unroll 8
        for (int d = 0; d < DD; d++) {
            float df = s_A[i * 65 + d] - s_A[j * 65 + d];
            d2 = fmaf(df, df, d2);
        }
        m = fmaxf(m, (si + s_Si[j]) / sqrtf(d2));
    }
#pragma unroll
    for (int o = 16; o; o >>= 1) m = fmaxf(m, __shfl_xor_sync(0xffffffffu, m, o));
    if ((tid & 31) == 0) s_red[tid >> 5] = m;
    __syncthreads();

    if (tid == 0) {
        float mm = s_red[0];
#pragma unroll
        for (int u = 1; u < RTPB / 32; u++) mm = fmaxf(mm, s_red[u]);
        g_rowmax[i] = mm;
        __threadfence();
        unsigned t = atomicAdd(&g_done, 1u);
        s_last = (t == KC - 1) ? 1 : 0;
    }
    __syncthreads();

    if (s_last) {                                 // last block: finish + clean
        __threadfence();
        volatile float* rm = g_rowmax;
        float v = (tid < KC) ? rm[tid] : 0.0f;
        if (tid < 128) {
#pragma unroll
            for (int o = 16; o; o >>= 1) v += __shfl_xor_sync(0xffffffffu, v, o);
            if ((tid & 31) == 0) s_red[tid >> 5] = v;
        }
        __syncthreads();
        // self-clean the blob for the next replay (all blocks are done:
        // they incremented the ticket only after their last G_SUM read)
        for (int idx = tid; idx < KC * DD + 2 * KC; idx += RTPB)
            g_blob[idx] = 0.0f;
        if (tid == 0) {
            out[0] = (s_red[0] + s_red[1] + s_red[2] + s_red[3]) / (float)KC;
            g_done = 0;                           // self-reset for next replay
        }
    }
}

// ---------------------------------------------------------------------------
extern "C" void kernel_launch(void* const* d_in, const int* in_sizes, int n_in,
                              void* d_out, int out_size) {
    const float* data;
    const void*  cl;
    int          n;
    if (in_sizes[0] >= in_sizes[1]) {
        data = (const float*)d_in[0]; cl = d_in[1]; n = in_sizes[1];
    } else {
        data = (const float*)d_in[1]; cl = d_in[0]; n = in_sizes[0];
    }

    // g_blob is zeroed at module load and self-cleaned by k_rows each run:
    // no memset node needed.
    k_accum<<<NBLK, TPB>>>(data, cl, n);
    k_rows <<<KC, RTPB>>>((float*)d_out);
}

// round 15
// speedup vs baseline: 1.3854x; 1.0222x over previous
#include <cuda_runtime.h>

#define KC   100
#define DD   64
#define CAP  224
#define WPB  25
#define TPB  800
#define NBLK 148
#define RTPB 1024            // k_rows block size (32 warps -> latency hiding)

// One contiguous zeroed blob: [ g_sum KC*DD | g_sumsq KC | g_cnti KC ]
// Zero-initialized at module load; SELF-CLEANED by k_rows' last block.
// 16B-aligned so k_rows can stage A with LDG.128.
__device__ __align__(16) float g_blob[KC * DD + KC + KC];
__device__ float    g_rowmax[KC];
__device__ unsigned g_done;          // self-resetting ticket (starts 0)

#define G_SUM   (g_blob)
#define G_SUMSQ (g_blob + KC * DD)
#define G_CNTI  ((int*)(g_blob + KC * DD + KC))

// ---------------------------------------------------------------------------
// Per-cluster accumulate: pair-packed LDG.128 gathers, batch-8 MLP.
// (FROZEN: the 97.1us scheduling is fragile — do not touch.)
// ---------------------------------------------------------------------------
__device__ __forceinline__ void accum_cluster(const float4* __restrict__ d4s,
                                              const unsigned short* __restrict__ lst,
                                              int len, int sub, int half,
                                              float4& A, float& Q) {
    int i = 0;
    for (; i + 16 <= len; i += 16) {
        int e0 = lst[i + 0  + half], e1 = lst[i + 2  + half];
        int e2 = lst[i + 4  + half], e3 = lst[i + 6  + half];
        int e4 = lst[i + 8  + half], e5 = lst[i + 10 + half];
        int e6 = lst[i + 12 + half], e7 = lst[i + 14 + half];
        float4 v0 = __ldcs(d4s + e0 * 16 + sub);
        float4 v1 = __ldcs(d4s + e1 * 16 + sub);
        float4 v2 = __ldcs(d4s + e2 * 16 + sub);
        float4 v3 = __ldcs(d4s + e3 * 16 + sub);
        float4 v4 = __ldcs(d4s + e4 * 16 + sub);
        float4 v5 = __ldcs(d4s + e5 * 16 + sub);
        float4 v6 = __ldcs(d4s + e6 * 16 + sub);
        float4 v7 = __ldcs(d4s + e7 * 16 + sub);
        A.x += v0.x + v1.x + v2.x + v3.x + v4.x + v5.x + v6.x + v7.x;
        A.y += v0.y + v1.y + v2.y + v3.y + v4.y + v5.y + v6.y + v7.y;
        A.z += v0.z + v1.z + v2.z + v3.z + v4.z + v5.z + v6.z + v7.z;
        A.w += v0.w + v1.w + v2.w + v3.w + v4.w + v5.w + v6.w + v7.w;
        Q = fmaf(v0.x, v0.x, Q); Q = fmaf(v0.y, v0.y, Q);
        Q = fmaf(v0.z, v0.z, Q); Q = fmaf(v0.w, v0.w, Q);
        Q = fmaf(v1.x, v1.x, Q); Q = fmaf(v1.y, v1.y, Q);
        Q = fmaf(v1.z, v1.z, Q); Q = fmaf(v1.w, v1.w, Q);
        Q = fmaf(v2.x, v2.x, Q); Q = fmaf(v2.y, v2.y, Q);
        Q = fmaf(v2.z, v2.z, Q); Q = fmaf(v2.w, v2.w, Q);
        Q = fmaf(v3.x, v3.x, Q); Q = fmaf(v3.y, v3.y, Q);
        Q = fmaf(v3.z, v3.z, Q); Q = fmaf(v3.w, v3.w, Q);
        Q = fmaf(v4.x, v4.x, Q); Q = fmaf(v4.y, v4.y, Q);
        Q = fmaf(v4.z, v4.z, Q); Q = fmaf(v4.w, v4.w, Q);
        Q = fmaf(v5.x, v5.x, Q); Q = fmaf(v5.y, v5.y, Q);
        Q = fmaf(v5.z, v5.z, Q); Q = fmaf(v5.w, v5.w, Q);
        Q = fmaf(v6.x, v6.x, Q); Q = fmaf(v6.y, v6.y, Q);
        Q = fmaf(v6.z, v6.z, Q); Q = fmaf(v6.w, v6.w, Q);
        Q = fmaf(v7.x, v7.x, Q); Q = fmaf(v7.y, v7.y, Q);
        Q = fmaf(v7.z, v7.z, Q); Q = fmaf(v7.w, v7.w, Q);
    }
    for (; i + 2 <= len; i += 2) {
        int e = lst[i + half];
        float4 v = __ldcs(d4s + e * 16 + sub);
        A.x += v.x; A.y += v.y; A.z += v.z; A.w += v.w;
        Q = fmaf(v.x, v.x, Q); Q = fmaf(v.y, v.y, Q);
        Q = fmaf(v.z, v.z, Q); Q = fmaf(v.w, v.w, Q);
    }
    if (i < len && half == 0) {
        int e = lst[i];
        float4 v = __ldcs(d4s + e * 16 + sub);
        A.x += v.x; A.y += v.y; A.z += v.z; A.w += v.w;
        Q = fmaf(v.x, v.x, Q); Q = fmaf(v.y, v.y, Q);
        Q = fmaf(v.z, v.z, Q); Q = fmaf(v.w, v.w, Q);
    }
}

// ---------------------------------------------------------------------------
// Kernel 1: one contiguous range per block. Bin once -> measured snake
// assignment -> register accumulate -> REDG flush. (FROZEN.)
// ---------------------------------------------------------------------------
__global__ __launch_bounds__(TPB, 1) void k_accum(const float* __restrict__ data,
                                                  const void* __restrict__ cl,
                                                  int n) {
    __shared__ unsigned short s_list[KC][CAP];   // 44.8 KB
    __shared__ int s_cnt[KC];
    __shared__ int s_asg[WPB][4];
    __shared__ int s_gc[WPB];
    __shared__ int s_is64;

    const int tid  = threadIdx.x;
    const int lane = tid & 31;
    const int w    = tid >> 5;
    const int sub  = lane & 15;
    const int half = lane >> 4;
    const unsigned FULL = 0xffffffffu;

    const int share = (n + NBLK - 1) / NBLK;
    const long long start = (long long)blockIdx.x * share;
    if (start >= n) return;
    const int bn = (int)min((long long)share, (long long)n - start);

    // ---- label-width detection (front of array; identical in all blocks)
    if (tid == 0) s_is64 = 1;
    for (int c = tid; c < KC; c += TPB) s_cnt[c] = 0;
    if (tid < WPB) s_gc[tid] = 0;
    __syncthreads();
    {
        int lim = min(64, (n - 1) / 2);
        if (tid < lim && ((const int*)cl)[2 * tid + 1] != 0)
            atomicAnd(&s_is64, 0);
    }
    __syncthreads();

    const int is64 = s_is64;
    const long long* cl64 = (const long long*)cl + start;
    const int*       cl32 = (const int*)cl + start;
    const float4*    d4s  = (const float4*)data + start * 16;

    // ---- bin (labels read once) ----------------------------------------
    for (int i = tid; i < bn; i += TPB) {
        int c = is64 ? (int)__ldg(cl64 + i) : __ldg(cl32 + i);
        int pos = atomicAdd(&s_cnt[c], 1);
        if (pos < CAP) {
            s_list[c][pos] = (unsigned short)i;
        } else {                                   // astronomically rare
            const float4* r = d4s + i * 16;
            float qq = 0.0f;
            for (int u = 0; u < 16; u++) {
                float4 v = __ldg(r + u);
                atomicAdd(&G_SUM[c * DD + u * 4 + 0], v.x);
                atomicAdd(&G_SUM[c * DD + u * 4 + 1], v.y);
                atomicAdd(&G_SUM[c * DD + u * 4 + 2], v.z);
                atomicAdd(&G_SUM[c * DD + u * 4 + 3], v.w);
                qq = fmaf(v.x, v.x, qq); qq = fmaf(v.y, v.y, qq);
                qq = fmaf(v.z, v.z, qq); qq = fmaf(v.w, v.w, qq);
            }
            atomicAdd(&G_SUMSQ[c], qq);
            atomicAdd(&G_CNTI[c], 1);
        }
    }
    __syncthreads();

    // ---- measured assignment: rank clusters by count, snake-deal to warps
    if (tid < KC) {
        int cc = s_cnt[tid];
        int r = 0;
        for (int j = 0; j < KC; j++) {
            int cj = s_cnt[j];
            r += (cj > cc) || (cj == cc && j < tid);
        }
        int q = r / WPB, p = r % WPB;
        int g = (q & 1) ? (WPB - 1 - p) : p;
        int slot = atomicAdd(&s_gc[g], 1);
        s_asg[g][slot] = tid;
        atomicAdd(&G_CNTI[tid], min(cc, CAP));
    }
    __syncthreads();

    // ---- accumulate: warp handles its 4 assigned clusters ---------------
    const int c0 = s_asg[w][0], c1 = s_asg[w][1];
    const int c2 = s_asg[w][2], c3 = s_asg[w][3];
    float4 a0 = {0,0,0,0}, a1 = {0,0,0,0}, a2 = {0,0,0,0}, a3 = {0,0,0,0};
    float  q0 = 0, q1 = 0, q2 = 0, q3 = 0;
    accum_cluster(d4s, s_list[c0], min(s_cnt[c0], CAP), sub, half, a0, q0);
    accum_cluster(d4s, s_list[c1], min(s_cnt[c1], CAP), sub, half, a1, q1);
    accum_cluster(d4s, s_list[c2], min(s_cnt[c2], CAP), sub, half, a2, q2);
    accum_cluster(d4s, s_list[c3], min(s_cnt[c3], CAP), sub, half, a3, q3);

    // ---- flush ----------------------------------------------------------
#define FLUSH(C, A, Q)                                                       \
    {                                                                        \
        A.x += __shfl_xor_sync(FULL, A.x, 16);                               \
        A.y += __shfl_xor_sync(FULL, A.y, 16);                               \
        A.z += __shfl_xor_sync(FULL, A.z, 16);                               \
        A.w += __shfl_xor_sync(FULL, A.w, 16);                               \
        float qq = Q;                                                        \
        for (int o = 16; o; o >>= 1) qq += __shfl_xor_sync(FULL, qq, o);     \
        if (lane < 16) {                                                     \
            float* dst = G_SUM + (C) * DD + sub * 4;                         \
            atomicAdd(dst + 0, A.x);                                         \
            atomicAdd(dst + 1, A.y);                                         \
            atomicAdd(dst + 2, A.z);                                         \
            atomicAdd(dst + 3, A.w);                                         \
        }                                                                    \
        if (lane == 0) atomicAdd(&G_SUMSQ[C], qq);                           \
    }
    FLUSH(c0, a0, q0)
    FLUSH(c1, a1, q1)
    FLUSH(c2, a2, q2)
    FLUSH(c3, a3, q3)
#undef FLUSH
}

// ---------------------------------------------------------------------------
// Kernel 2: one block per cluster-row, 1024 threads; float4 staging of A
// (4x fewer L2 loads in the critical chain). Si algebraic from staged A.
// Last ticketed block finishes the scalar and re-zeros g_blob.
// ---------------------------------------------------------------------------
__global__ __launch_bounds__(RTPB) void k_rows(float* __restrict__ out) {
    __shared__ float s_A[KC * (DD + 1)];   // padded 65: conflict-free j-reads
    __shared__ float s_Si[KC];
    __shared__ float s_rcp[KC];
    __shared__ float s_red[RTPB / 32];
    __shared__ int   s_last;

    const int tid = threadIdx.x;

    if (tid < KC) s_rcp[tid] = 1.0f / ((float)__ldg(&G_CNTI[tid]) + 1.0f);
    __syncthreads();

    // stage A via LDG.128: 1600 float4 loads instead of 6400 scalar loads
    {
        const float4* gs4 = (const float4*)G_SUM;      // KC*16 float4
        for (int idx = tid; idx < KC * 16; idx += RTPB) {
            int k  = idx >> 4;
            int d4 = (idx & 15) << 2;
            float4 v = __ldg(gs4 + idx);
            float  r = s_rcp[k];
            float* dst = &s_A[k * 65 + d4];
            dst[0] = (v.x + 0.001f) * r;
            dst[1] = (v.y + 0.001f) * r;
            dst[2] = (v.z + 0.001f) * r;
            dst[3] = (v.w + 0.001f) * r;
        }
    }
    __syncthreads();

    // Si from A only: dot(A,S) = (n+1)*sum(A^2) - 0.001*sum(A)
    for (int k = tid; k < KC; k += RTPB) {
        float nk = (float)__ldg(&G_CNTI[k]);
        float a2 = 0.0f, sa = 0.0f;
#pragma unroll 8
        for (int d = 0; d < DD; d++) {
            float av = s_A[k * 65 + d];
            a2 = fmaf(av, av, a2);
            sa += av;
        }
        float dot = (nk + 1.0f) * a2 - 0.001f * sa;
        float ss = __ldg(&G_SUMSQ[k]) - 2.0f * dot + nk * a2;
        s_Si[k] = sqrtf((0.001f + ss) * s_rcp[k]);
    }
    __syncthreads();

    const int i = blockIdx.x;
    const float si = s_Si[i];
    float m = 0.0f;
    for (int j = tid; j < KC; j += RTPB) {
        if (j == i) continue;
        float d2 = 0.0f;
#pragma unroll 8
        for (int d = 0; d < DD; d++) {
            float df = s_A[i * 65 + d] - s_A[j * 65 + d];
            d2 = fmaf(df, df, d2);
        }
        m = fmaxf(m, (si + s_Si[j]) / sqrtf(d2));
    }
#pragma unroll
    for (int o = 16; o; o >>= 1) m = fmaxf(m, __shfl_xor_sync(0xffffffffu, m, o));
    if ((tid & 31) == 0) s_red[tid >> 5] = m;
    __syncthreads();

    if (tid == 0) {
        float mm = s_red[0];
#pragma unroll
        for (int u = 1; u < RTPB / 32; u++) mm = fmaxf(mm, s_red[u]);
        g_rowmax[i] = mm;
        __threadfence();
        unsigned t = atomicAdd(&g_done, 1u);
        s_last = (t == KC - 1) ? 1 : 0;
    }
    __syncthreads();

    if (s_last) {                                 // last block: finish + clean
        __threadfence();
        volatile float* rm = g_rowmax;
        float v = (tid < KC) ? rm[tid] : 0.0f;
        if (tid < 128) {
#pragma unroll
            for (int o = 16; o; o >>= 1) v += __shfl_xor_sync(0xffffffffu, v, o);
            if ((tid & 31) == 0) s_red[tid >> 5] = v;
        }
        __syncthreads();
        // self-clean the blob for the next replay (all blocks ticketed after
        // their last G_SUM read, so no reader can race this)
        for (int idx = tid; idx < KC * DD + 2 * KC; idx += RTPB)
            g_blob[idx] = 0.0f;
        if (tid == 0) {
            out[0] = (s_red[0] + s_red[1] + s_red[2] + s_red[3]) / (float)KC;
            g_done = 0;                           // self-reset for next replay
        }
    }
}

// ---------------------------------------------------------------------------
extern "C" void kernel_launch(void* const* d_in, const int* in_sizes, int n_in,
                              void* d_out, int out_size) {
    const float* data;
    const void*  cl;
    int          n;
    if (in_sizes[0] >= in_sizes[1]) {
        data = (const float*)d_in[0]; cl = d_in[1]; n = in_sizes[1];
    } else {
        data = (const float*)d_in[1]; cl = d_in[0]; n = in_sizes[0];
    }

    // g_blob zeroed at module load and self-cleaned by k_rows each run.
    k_accum<<<NBLK, TPB>>>(data, cl, n);
    k_rows <<<KC, RTPB>>>((float*)d_out);
}